// round 1
// baseline (speedup 1.0000x reference)
#include <cuda_runtime.h>
#include <math.h>

// ---------------- problem dims (fixed) ----------------
#define Bdim   2
#define Tdim   4096
#define Hdim   2048
#define NHdim  16
#define HDdim  128
#define Mdim   8192          // B*T
#define INTERd 8192
#define KCONV  3
#define EPSf   1e-6f
#define NCHUNK 64
#define CHUNK  64            // NCHUNK*CHUNK == Tdim

// ---------------- scratch (device globals; no cudaMalloc allowed) ----------
__device__ float  g_wc[(size_t)KCONV * Hdim * Hdim];     // conv weight [k][i][o]
__device__ float  g_norm[(size_t)Mdim * Hdim];           // rmsnorm out (reused)
__device__ float  g_x[(size_t)Mdim * Hdim];              // conv out
__device__ float  g_q[(size_t)Mdim * Hdim];
__device__ float  g_v[(size_t)Mdim * Hdim];
__device__ float  g_scan[(size_t)Mdim * Hdim];           // q*state
__device__ float  g_h2[(size_t)Mdim * Hdim];             // residual-1 result
__device__ float  g_inter[(size_t)Mdim * INTERd];        // mlp intermediate
__device__ float  g_dt[Mdim * NHdim];                    // beta = dt
__device__ float  g_p[Bdim * NHdim * Tdim];              // cumprod(alpha)
__device__ double g_S[Bdim * NHdim * NCHUNK * HDdim];    // per-chunk partial sums
__device__ double g_carry[Bdim * NHdim * NCHUNK * HDdim];
__device__ float  g_invf[HDdim / 2];

// ---------------- small init kernels ----------------
__global__ void init_invf_kernel() {
    int j = threadIdx.x;
    if (j < HDdim / 2) {
        // inv_freq[j] = 10000^(-(2j)/128), computed in double then cast (matches fp32 ref within ~1 ulp)
        g_invf[j] = (float)exp(-((double)j / 64.0) * log(10000.0));
    }
}

__global__ void pack_convw_kernel(const float* __restrict__ conv_w) {
    size_t idx = (size_t)blockIdx.x * blockDim.x + threadIdx.x;
    size_t total = (size_t)KCONV * Hdim * Hdim;
    if (idx >= total) return;
    int o = (int)(idx % Hdim);
    size_t rest = idx / Hdim;
    int i = (int)(rest % Hdim);
    int k = (int)(rest / Hdim);
    // g_wc[(k*H + i)*H + o] = conv_w[o][i][k]
    g_wc[idx] = conv_w[((size_t)o * Hdim + i) * KCONV + k];
}

// ---------------- rmsnorm ----------------
__global__ void rmsnorm_kernel(const float* __restrict__ x, const float* __restrict__ w,
                               float* __restrict__ y) {
    int m = blockIdx.x;
    const float4* xr = reinterpret_cast<const float4*>(x + (size_t)m * Hdim);
    const float4* wr = reinterpret_cast<const float4*>(w);
    int t = threadIdx.x;           // 256 threads, 512 float4s
    float4 v0 = xr[t];
    float4 v1 = xr[t + 256];
    float ss = v0.x*v0.x + v0.y*v0.y + v0.z*v0.z + v0.w*v0.w
             + v1.x*v1.x + v1.y*v1.y + v1.z*v1.z + v1.w*v1.w;
    __shared__ float red[8];
    #pragma unroll
    for (int off = 16; off; off >>= 1) ss += __shfl_down_sync(0xffffffffu, ss, off);
    if ((t & 31) == 0) red[t >> 5] = ss;
    __syncthreads();
    if (t < 32) {
        float s = (t < 8) ? red[t] : 0.f;
        #pragma unroll
        for (int off = 4; off; off >>= 1) s += __shfl_down_sync(0xffffffffu, s, off);
        if (t == 0) red[0] = s;
    }
    __syncthreads();
    float scale = rsqrtf(red[0] * (1.0f / Hdim) + EPSf);
    float4 w0 = wr[t], w1 = wr[t + 256];
    float4 o0, o1;
    o0.x = v0.x * scale * w0.x; o0.y = v0.y * scale * w0.y;
    o0.z = v0.z * scale * w0.z; o0.w = v0.w * scale * w0.w;
    o1.x = v1.x * scale * w1.x; o1.y = v1.y * scale * w1.y;
    o1.z = v1.z * scale * w1.z; o1.w = v1.w * scale * w1.w;
    float4* yr = reinterpret_cast<float4*>(y + (size_t)m * Hdim);
    yr[t] = o0;
    yr[t + 256] = o1;
}

// ---------------- SGEMM: C[M,N] = A[M,K] @ B[K,N] (+bias)(silu)(+resid) ----------------
// CONV mode: logical A is [M, 3H] with A'[m, k*H+i] = attn_in[row(m)-2+k, i], zero below batch start.
#define BM 128
#define BN 128
#define BKg 8
#define TM 8
#define TN 8

template<bool CONV, bool BIAS, bool SILU, bool RESID>
__global__ __launch_bounds__(256, 2)
void sgemm_kernel(const float* __restrict__ A, const float* __restrict__ B,
                  float* __restrict__ C, int M, int N, int Kd,
                  const float* __restrict__ bias, const float* __restrict__ resid) {
    __shared__ float As[BKg][BM];
    __shared__ float Bs[BKg][BN];
    const int tid = threadIdx.x;
    const int tx = tid & 15;
    const int ty = tid >> 4;
    const int m_base = blockIdx.y * BM;
    const int n_base = blockIdx.x * BN;

    const int a_row = tid >> 1;          // 0..127
    const int a_col = (tid & 1) * 4;     // 0 or 4
    const int b_row = tid >> 5;          // 0..7
    const int b_col = (tid & 31) * 4;    // 0..124

    float acc[TM][TN];
    #pragma unroll
    for (int i = 0; i < TM; i++)
        #pragma unroll
        for (int j = 0; j < TN; j++) acc[i][j] = 0.f;

    for (int k0 = 0; k0 < Kd; k0 += BKg) {
        float4 av;
        {
            int kk = k0 + a_col;
            int m = m_base + a_row;
            if (CONV) {
                int kidx = kk >> 11;         // conv tap 0..2  (H=2048)
                int i = kk & (Hdim - 1);
                int t = m & (Tdim - 1);
                if (t - 2 + kidx >= 0) {
                    int src = m - 2 + kidx;
                    av = *reinterpret_cast<const float4*>(A + (size_t)src * Hdim + i);
                } else {
                    av = make_float4(0.f, 0.f, 0.f, 0.f);
                }
            } else {
                av = *reinterpret_cast<const float4*>(A + (size_t)m * Kd + kk);
            }
        }
        As[a_col + 0][a_row] = av.x;
        As[a_col + 1][a_row] = av.y;
        As[a_col + 2][a_row] = av.z;
        As[a_col + 3][a_row] = av.w;
        float4 bv = *reinterpret_cast<const float4*>(B + (size_t)(k0 + b_row) * N + n_base + b_col);
        *reinterpret_cast<float4*>(&Bs[b_row][b_col]) = bv;
        __syncthreads();
        #pragma unroll
        for (int k = 0; k < BKg; k++) {
            float4 a0 = *reinterpret_cast<const float4*>(&As[k][ty * TM]);
            float4 a1 = *reinterpret_cast<const float4*>(&As[k][ty * TM + 4]);
            float4 b0 = *reinterpret_cast<const float4*>(&Bs[k][tx * TN]);
            float4 b1 = *reinterpret_cast<const float4*>(&Bs[k][tx * TN + 4]);
            float ar[TM] = {a0.x, a0.y, a0.z, a0.w, a1.x, a1.y, a1.z, a1.w};
            float br[TN] = {b0.x, b0.y, b0.z, b0.w, b1.x, b1.y, b1.z, b1.w};
            #pragma unroll
            for (int i = 0; i < TM; i++)
                #pragma unroll
                for (int j = 0; j < TN; j++)
                    acc[i][j] += ar[i] * br[j];
        }
        __syncthreads();
    }

    #pragma unroll
    for (int i = 0; i < TM; i++) {
        int m = m_base + ty * TM + i;
        #pragma unroll
        for (int j = 0; j < TN; j++) {
            int n = n_base + tx * TN + j;
            float c = acc[i][j];
            if (BIAS)  c += bias[n];
            if (SILU)  c = c * (1.0f / (1.0f + expf(-c)));
            if (RESID) c += resid[(size_t)m * N + n];
            C[(size_t)m * N + n] = c;
        }
    }
}

// ---------------- dt = softplus(h @ w_dt + b_dt + dt_bias) ----------------
__global__ void dt_kernel(const float* __restrict__ w_dt, const float* __restrict__ b_dt,
                          const float* __restrict__ dt_bias) {
    int m = blockIdx.x;
    int nh = threadIdx.x >> 5;
    int lane = threadIdx.x & 31;
    const float* hr = g_norm + (size_t)m * Hdim;
    float s = 0.f;
    for (int k = lane; k < Hdim; k += 32) s += hr[k] * w_dt[(size_t)k * NHdim + nh];
    #pragma unroll
    for (int off = 16; off; off >>= 1) s += __shfl_down_sync(0xffffffffu, s, off);
    if (lane == 0) {
        float x = s + b_dt[nh] + dt_bias[nh];
        // stable softplus
        float d = fmaxf(x, 0.f) + log1pf(expf(-fabsf(x)));
        g_dt[m * NHdim + nh] = d;
    }
}

// ---------------- p = cumprod(exp(A*dt)) per (b,nh); 32 warps, 1 block ----------------
__global__ void p_scan_kernel(const float* __restrict__ A_log) {
    int warp = threadIdx.x >> 5;        // bnh 0..31
    int lane = threadIdx.x & 31;
    int b = warp >> 4, nh = warp & (NHdim - 1);
    float Anh = -expf(A_log[nh]);
    int t0 = lane * (Tdim / 32);        // 128 consecutive t per lane
    float prod = 1.f;
    for (int i = 0; i < Tdim / 32; i++) {
        int t = t0 + i;
        float d = g_dt[(b * Tdim + t) * NHdim + nh];
        prod *= expf(Anh * d);
    }
    // inclusive product scan across lanes -> exclusive
    float x = prod;
    #pragma unroll
    for (int off = 1; off < 32; off <<= 1) {
        float y = __shfl_up_sync(0xffffffffu, x, off);
        if (lane >= off) x *= y;
    }
    float excl = __shfl_up_sync(0xffffffffu, x, 1);
    if (lane == 0) excl = 1.f;
    float running = excl;
    float* prow = g_p + warp * Tdim;
    for (int i = 0; i < Tdim / 32; i++) {
        int t = t0 + i;
        float d = g_dt[(b * Tdim + t) * NHdim + nh];
        running *= expf(Anh * d);
        prow[t] = running;
    }
}

// ---------------- chunked scan of s = cumsum(beta*v/(p+EPS)) ----------------
__global__ void scan_partial_kernel() {
    int blk = blockIdx.x;                 // bnh*NCHUNK + c
    int bnh = blk >> 6;
    int c = blk & (NCHUNK - 1);
    int b = bnh >> 4, nh = bnh & (NHdim - 1);
    int hd = threadIdx.x;
    const float* prow = g_p + bnh * Tdim;
    double s = 0.0;
    int t0 = c * CHUNK;
    for (int i = 0; i < CHUNK; i++) {
        int t = t0 + i;
        int m = b * Tdim + t;
        float beta = g_dt[m * NHdim + nh];
        float pv = prow[t];
        float v = g_v[(size_t)m * Hdim + nh * HDdim + hd];
        s += (double)((beta * v) / (pv + EPSf));
    }
    g_S[(size_t)blk * HDdim + hd] = s;
}

__global__ void scan_carry_kernel() {
    int bnh = blockIdx.x;
    int hd = threadIdx.x;
    double carry = 0.0;
    for (int c = 0; c < NCHUNK; c++) {
        size_t idx = ((size_t)bnh * NCHUNK + c) * HDdim + hd;
        g_carry[idx] = carry;
        carry += g_S[idx];
    }
}

__global__ void scan_final_kernel() {
    int blk = blockIdx.x;
    int bnh = blk >> 6;
    int c = blk & (NCHUNK - 1);
    int b = bnh >> 4, nh = bnh & (NHdim - 1);
    int hd = threadIdx.x;
    const float* prow = g_p + bnh * Tdim;
    double s = g_carry[(size_t)blk * HDdim + hd];
    int t0 = c * CHUNK;
    for (int i = 0; i < CHUNK; i++) {
        int t = t0 + i;
        int m = b * Tdim + t;
        float beta = g_dt[m * NHdim + nh];
        float pv = prow[t];
        size_t vidx = (size_t)m * Hdim + nh * HDdim + hd;
        float v = g_v[vidx];
        s += (double)((beta * v) / (pv + EPSf));
        float state = (float)((double)pv * s);
        g_scan[vidx] = g_q[vidx] * state;
    }
}

// ---------------- RoPE (in place on g_q) ----------------
__global__ void rope_kernel(const int* __restrict__ pos_ids) {
    size_t idx = (size_t)blockIdx.x * blockDim.x + threadIdx.x;   // pair index
    size_t total = (size_t)Mdim * (Hdim / 2);
    if (idx >= total) return;
    int m = (int)(idx >> 10);           // Hdim/2 = 1024 pairs per row
    int r = (int)(idx & 1023);
    int nh = r >> 6;
    int j = r & 63;
    int d0 = 2 * j;
    float pos = (float)pos_ids[m];
    size_t base = (size_t)m * Hdim + nh * HDdim + d0;
    float q0 = g_q[base], q1 = g_q[base + 1];
    // emb[d] uses inv_freq[d % 64]; even/odd lanes get different angles
    float a0 = pos * g_invf[d0 & 63];
    float a1 = pos * g_invf[(d0 + 1) & 63];
    float c0 = cosf(a0), s0 = sinf(a0);
    float c1 = cosf(a1), s1 = sinf(a1);
    g_q[base]     = q0 * c0 - q1 * s0;
    g_q[base + 1] = q1 * c1 + q0 * s1;
}

// ---------------- launch ----------------
static void launch_gemm(const float* A, const float* B, float* C, int M, int N, int Kd,
                        const float* bias, const float* resid, bool conv, bool silu) {
    dim3 grid(N / BN, M / BM), block(256);
    if (conv)       sgemm_kernel<true,  true,  false, false><<<grid, block>>>(A, B, C, M, N, Kd, bias, nullptr);
    else if (silu)  sgemm_kernel<false, false, true,  false><<<grid, block>>>(A, B, C, M, N, Kd, nullptr, nullptr);
    else if (resid) sgemm_kernel<false, false, false, true ><<<grid, block>>>(A, B, C, M, N, Kd, nullptr, resid);
    else            sgemm_kernel<false, false, false, false><<<grid, block>>>(A, B, C, M, N, Kd, nullptr, nullptr);
}

extern "C" void kernel_launch(void* const* d_in, const int* in_sizes, int n_in,
                              void* d_out, int out_size) {
    const float* hidden  = (const float*)d_in[0];
    const int*   pos_ids = (const int*)  d_in[1];
    const float* conv_w  = (const float*)d_in[2];
    const float* conv_b  = (const float*)d_in[3];
    const float* wq      = (const float*)d_in[4];
    const float* wv      = (const float*)d_in[5];
    const float* w_dt    = (const float*)d_in[6];
    const float* b_dt    = (const float*)d_in[7];
    const float* A_log   = (const float*)d_in[8];
    const float* dt_bias = (const float*)d_in[9];
    const float* wo      = (const float*)d_in[10];
    const float* w1      = (const float*)d_in[11];
    const float* w2      = (const float*)d_in[12];
    const float* norm1_w = (const float*)d_in[13];
    const float* norm2_w = (const float*)d_in[14];
    float* out = (float*)d_out;

    float *p_wc, *p_norm, *p_x, *p_q, *p_v, *p_scan, *p_h2, *p_inter;
    cudaGetSymbolAddress((void**)&p_wc,    g_wc);
    cudaGetSymbolAddress((void**)&p_norm,  g_norm);
    cudaGetSymbolAddress((void**)&p_x,     g_x);
    cudaGetSymbolAddress((void**)&p_q,     g_q);
    cudaGetSymbolAddress((void**)&p_v,     g_v);
    cudaGetSymbolAddress((void**)&p_scan,  g_scan);
    cudaGetSymbolAddress((void**)&p_h2,    g_h2);
    cudaGetSymbolAddress((void**)&p_inter, g_inter);

    // init
    init_invf_kernel<<<1, 64>>>();
    {
        size_t total = (size_t)KCONV * Hdim * Hdim;
        pack_convw_kernel<<<(unsigned)((total + 255) / 256), 256>>>(conv_w);
    }

    // attn branch
    rmsnorm_kernel<<<Mdim, 256>>>(hidden, norm1_w, p_norm);
    launch_gemm(p_norm, p_wc, p_x, Mdim, Hdim, KCONV * Hdim, conv_b, nullptr, true, false); // conv
    launch_gemm(p_x, wq, p_q, Mdim, Hdim, Hdim, nullptr, nullptr, false, false);
    launch_gemm(p_x, wv, p_v, Mdim, Hdim, Hdim, nullptr, nullptr, false, false);
    {
        size_t pairs = (size_t)Mdim * (Hdim / 2);
        rope_kernel<<<(unsigned)((pairs + 255) / 256), 256>>>(pos_ids);
    }
    dt_kernel<<<Mdim, NHdim * 32>>>(w_dt, b_dt, dt_bias);
    p_scan_kernel<<<1, 1024>>>(A_log);
    scan_partial_kernel<<<Bdim * NHdim * NCHUNK, HDdim>>>();
    scan_carry_kernel<<<Bdim * NHdim, HDdim>>>();
    scan_final_kernel<<<Bdim * NHdim * NCHUNK, HDdim>>>();
    launch_gemm(p_scan, wo, p_h2, Mdim, Hdim, Hdim, nullptr, hidden, false, false);  // + residual

    // mlp branch
    rmsnorm_kernel<<<Mdim, 256>>>(p_h2, norm2_w, p_norm);
    launch_gemm(p_norm, w1, p_inter, Mdim, INTERd, Hdim, nullptr, nullptr, false, true);   // silu
    launch_gemm(p_inter, w2, out, Mdim, Hdim, INTERd, nullptr, p_h2, false, false);        // + residual
}

// round 2
// speedup vs baseline: 1.4795x; 1.4795x over previous
#include <cuda_runtime.h>
#include <math.h>
#include <stdint.h>

// ---------------- problem dims (fixed) ----------------
#define Bdim   2
#define Tdim   4096
#define Hdim   2048
#define NHdim  16
#define HDdim  128
#define Mdim   8192          // B*T
#define INTERd 8192
#define KCONV  3
#define EPSf   1e-6f
#define NCHUNK 64
#define CHUNK  64            // NCHUNK*CHUNK == Tdim

// ---------------- scratch (device globals; no cudaMalloc allowed) ----------
__device__ float  g_wc[(size_t)KCONV * Hdim * Hdim];     // conv weight [k][i][o]
__device__ float  g_norm[(size_t)Mdim * Hdim];           // rmsnorm out (reused)
__device__ float  g_x[(size_t)Mdim * Hdim];              // conv out
__device__ float  g_q[(size_t)Mdim * Hdim];
__device__ float  g_v[(size_t)Mdim * Hdim];
__device__ float  g_scan[(size_t)Mdim * Hdim];           // q*state
__device__ float  g_h2[(size_t)Mdim * Hdim];             // residual-1 result
__device__ float  g_inter[(size_t)Mdim * INTERd];        // mlp intermediate
__device__ float  g_dt[Mdim * NHdim];                    // beta = dt
__device__ float  g_p[Bdim * NHdim * Tdim];              // cumprod(alpha)
__device__ double g_S[Bdim * NHdim * NCHUNK * HDdim];    // per-chunk partial sums
__device__ double g_carry[Bdim * NHdim * NCHUNK * HDdim];
__device__ float  g_invf[HDdim / 2];

// ---------------- small init kernels ----------------
__global__ void init_invf_kernel() {
    int j = threadIdx.x;
    if (j < HDdim / 2) {
        g_invf[j] = (float)exp(-((double)j / 64.0) * log(10000.0));
    }
}

__global__ void pack_convw_kernel(const float* __restrict__ conv_w) {
    size_t idx = (size_t)blockIdx.x * blockDim.x + threadIdx.x;
    size_t total = (size_t)KCONV * Hdim * Hdim;
    if (idx >= total) return;
    int o = (int)(idx % Hdim);
    size_t rest = idx / Hdim;
    int i = (int)(rest % Hdim);
    int k = (int)(rest / Hdim);
    g_wc[idx] = conv_w[((size_t)o * Hdim + i) * KCONV + k];
}

// ---------------- rmsnorm ----------------
__global__ void rmsnorm_kernel(const float* __restrict__ x, const float* __restrict__ w,
                               float* __restrict__ y) {
    int m = blockIdx.x;
    const float4* xr = reinterpret_cast<const float4*>(x + (size_t)m * Hdim);
    const float4* wr = reinterpret_cast<const float4*>(w);
    int t = threadIdx.x;           // 256 threads, 512 float4s
    float4 v0 = xr[t];
    float4 v1 = xr[t + 256];
    float ss = v0.x*v0.x + v0.y*v0.y + v0.z*v0.z + v0.w*v0.w
             + v1.x*v1.x + v1.y*v1.y + v1.z*v1.z + v1.w*v1.w;
    __shared__ float red[8];
    #pragma unroll
    for (int off = 16; off; off >>= 1) ss += __shfl_down_sync(0xffffffffu, ss, off);
    if ((t & 31) == 0) red[t >> 5] = ss;
    __syncthreads();
    if (t < 32) {
        float s = (t < 8) ? red[t] : 0.f;
        #pragma unroll
        for (int off = 4; off; off >>= 1) s += __shfl_down_sync(0xffffffffu, s, off);
        if (t == 0) red[0] = s;
    }
    __syncthreads();
    float scale = rsqrtf(red[0] * (1.0f / Hdim) + EPSf);
    float4 w0 = wr[t], w1 = wr[t + 256];
    float4 o0, o1;
    o0.x = v0.x * scale * w0.x; o0.y = v0.y * scale * w0.y;
    o0.z = v0.z * scale * w0.z; o0.w = v0.w * scale * w0.w;
    o1.x = v1.x * scale * w1.x; o1.y = v1.y * scale * w1.y;
    o1.z = v1.z * scale * w1.z; o1.w = v1.w * scale * w1.w;
    float4* yr = reinterpret_cast<float4*>(y + (size_t)m * Hdim);
    yr[t] = o0;
    yr[t + 256] = o1;
}

// =====================================================================
// TF32 tensor-core GEMM (3xTF32 compensated): C[M,N] = A[M,K] @ B[K,N]
// CONV mode: logical A is [M, 3H], A'[m, k*H+i] = attn_in[row(m)-2+k, i],
// zero below batch start.
// =====================================================================
#define BM 128
#define BN 128
#define BKt 16
#define ASTR (BKt + 4)    // 20: conflict-free A-fragment lds
#define BSTR (BN + 8)     // 136: conflict-free B-fragment lds

__device__ __forceinline__ void cp_async16(void* dst, const void* src, int ssize) {
    uint32_t d = (uint32_t)__cvta_generic_to_shared(dst);
    asm volatile("cp.async.cg.shared.global [%0], [%1], 16, %2;\n"
                 :: "r"(d), "l"(src), "r"(ssize));
}

__device__ __forceinline__ void split_tf32(float x, uint32_t& hi, uint32_t& lo) {
    uint32_t h;
    asm("cvt.rna.tf32.f32 %0, %1;" : "=r"(h) : "f"(x));
    float r = x - __uint_as_float(h);
    asm("cvt.rna.tf32.f32 %0, %1;" : "=r"(lo) : "f"(r));
    hi = h;
}

__device__ __forceinline__ void mma_tf32(float* c, const uint32_t* a, const uint32_t* b) {
    asm volatile(
        "mma.sync.aligned.m16n8k8.row.col.f32.tf32.tf32.f32 "
        "{%0,%1,%2,%3}, {%4,%5,%6,%7}, {%8,%9}, {%0,%1,%2,%3};\n"
        : "+f"(c[0]), "+f"(c[1]), "+f"(c[2]), "+f"(c[3])
        : "r"(a[0]), "r"(a[1]), "r"(a[2]), "r"(a[3]), "r"(b[0]), "r"(b[1]));
}

template<bool CONV>
__device__ __forceinline__ void load_tile(float (*As)[ASTR], float (*Bs)[BSTR],
                                          const float* __restrict__ A,
                                          const float* __restrict__ B,
                                          int N, int Kd, int m_base, int n_base,
                                          int k0, int tid) {
    #pragma unroll
    for (int h = 0; h < 2; h++) {
        int idx = tid + h * 256;
        int m = idx >> 2;
        int kq = (idx & 3) * 4;
        const float* src;
        int ssize = 16;
        if (CONV) {
            int kk = k0 + kq;
            int kidx = kk >> 11;             // tap 0..2 (H=2048)
            int i = kk & (Hdim - 1);
            int gm = m_base + m;
            int t = gm & (Tdim - 1);
            if (t - 2 + kidx >= 0) {
                src = A + (size_t)(gm - 2 + kidx) * Hdim + i;
            } else {
                src = A;       // valid dummy address; zero-filled
                ssize = 0;
            }
        } else {
            src = A + (size_t)(m_base + m) * Kd + k0 + kq;
        }
        cp_async16(&As[m][kq], src, ssize);
    }
    #pragma unroll
    for (int h = 0; h < 2; h++) {
        int idx = tid + h * 256;
        int k = idx >> 5;
        int n4 = (idx & 31) * 4;
        cp_async16(&Bs[k][n4], B + (size_t)(k0 + k) * N + n_base + n4, 16);
    }
}

template<bool CONV, bool BIAS, bool SILU, bool RESID>
__global__ __launch_bounds__(256)
void mma_gemm_kernel(const float* __restrict__ A, const float* __restrict__ B,
                     float* __restrict__ C, int M, int N, int Kd,
                     const float* __restrict__ bias, const float* __restrict__ resid) {
    __shared__ __align__(16) float As[2][BM][ASTR];
    __shared__ __align__(16) float Bs[2][BKt][BSTR];

    const int tid = threadIdx.x;
    const int warp = tid >> 5;
    const int lane = tid & 31;
    const int gr = lane >> 2;     // groupID 0..7
    const int gc = lane & 3;      // threadInGroup 0..3
    const int wm = (warp >> 2) * 64;   // 0 / 64
    const int wn = (warp & 3) * 32;    // 0,32,64,96
    const int m_base = blockIdx.y * BM;
    const int n_base = blockIdx.x * BN;

    float acc[4][4][4];           // [mt][nt][4]
    #pragma unroll
    for (int i = 0; i < 4; i++)
        #pragma unroll
        for (int j = 0; j < 4; j++)
            #pragma unroll
            for (int r = 0; r < 4; r++) acc[i][j][r] = 0.f;

    const int ntiles = Kd / BKt;
    load_tile<CONV>(As[0], Bs[0], A, B, N, Kd, m_base, n_base, 0, tid);
    asm volatile("cp.async.commit_group;\n");

    for (int it = 0; it < ntiles; ++it) {
        if (it + 1 < ntiles) {
            load_tile<CONV>(As[(it + 1) & 1], Bs[(it + 1) & 1], A, B, N, Kd,
                            m_base, n_base, (it + 1) * BKt, tid);
            asm volatile("cp.async.commit_group;\n");
            asm volatile("cp.async.wait_group 1;\n");
        } else {
            asm volatile("cp.async.wait_group 0;\n");
        }
        __syncthreads();
        const int buf = it & 1;

        #pragma unroll
        for (int ks = 0; ks < BKt; ks += 8) {
            uint32_t Bh[4][2], Bl[4][2];
            #pragma unroll
            for (int nt = 0; nt < 4; nt++) {
                int col = wn + nt * 8 + gr;
                split_tf32(Bs[buf][ks + gc][col],     Bh[nt][0], Bl[nt][0]);
                split_tf32(Bs[buf][ks + gc + 4][col], Bh[nt][1], Bl[nt][1]);
            }
            #pragma unroll
            for (int mt = 0; mt < 4; mt++) {
                int r0 = wm + mt * 16 + gr;
                uint32_t ah[4], al[4];
                split_tf32(As[buf][r0][ks + gc],         ah[0], al[0]);
                split_tf32(As[buf][r0 + 8][ks + gc],     ah[1], al[1]);
                split_tf32(As[buf][r0][ks + gc + 4],     ah[2], al[2]);
                split_tf32(As[buf][r0 + 8][ks + gc + 4], ah[3], al[3]);
                #pragma unroll
                for (int nt = 0; nt < 4; nt++) {
                    mma_tf32(acc[mt][nt], al, Bh[nt]);
                    mma_tf32(acc[mt][nt], ah, Bl[nt]);
                    mma_tf32(acc[mt][nt], ah, Bh[nt]);
                }
            }
        }
        __syncthreads();
    }

    // epilogue
    #pragma unroll
    for (int mt = 0; mt < 4; mt++) {
        #pragma unroll
        for (int nt = 0; nt < 4; nt++) {
            int row0 = m_base + wm + mt * 16 + gr;
            int col  = n_base + wn + nt * 8 + gc * 2;
            #pragma unroll
            for (int half = 0; half < 2; half++) {
                int row = row0 + half * 8;
                float c0 = acc[mt][nt][half * 2 + 0];
                float c1 = acc[mt][nt][half * 2 + 1];
                if (BIAS) { c0 += bias[col]; c1 += bias[col + 1]; }
                if (SILU) {
                    c0 = c0 * (1.0f / (1.0f + expf(-c0)));
                    c1 = c1 * (1.0f / (1.0f + expf(-c1)));
                }
                if (RESID) {
                    const float2 r = *reinterpret_cast<const float2*>(
                        resid + (size_t)row * N + col);
                    c0 += r.x; c1 += r.y;
                }
                float2 o; o.x = c0; o.y = c1;
                *reinterpret_cast<float2*>(C + (size_t)row * N + col) = o;
            }
        }
    }
}

// ---------------- dt = softplus(h @ w_dt + b_dt + dt_bias) ----------------
__global__ void dt_kernel(const float* __restrict__ w_dt, const float* __restrict__ b_dt,
                          const float* __restrict__ dt_bias) {
    int m = blockIdx.x;
    int nh = threadIdx.x >> 5;
    int lane = threadIdx.x & 31;
    const float* hr = g_norm + (size_t)m * Hdim;
    float s = 0.f;
    for (int k = lane; k < Hdim; k += 32) s += hr[k] * w_dt[(size_t)k * NHdim + nh];
    #pragma unroll
    for (int off = 16; off; off >>= 1) s += __shfl_down_sync(0xffffffffu, s, off);
    if (lane == 0) {
        float x = s + b_dt[nh] + dt_bias[nh];
        float d = fmaxf(x, 0.f) + log1pf(expf(-fabsf(x)));
        g_dt[m * NHdim + nh] = d;
    }
}

// ---------------- p = cumprod(exp(A*dt)) per (b,nh) ----------------
__global__ void p_scan_kernel(const float* __restrict__ A_log) {
    int warp = threadIdx.x >> 5;        // bnh 0..31
    int lane = threadIdx.x & 31;
    int b = warp >> 4, nh = warp & (NHdim - 1);
    float Anh = -expf(A_log[nh]);
    int t0 = lane * (Tdim / 32);
    float prod = 1.f;
    for (int i = 0; i < Tdim / 32; i++) {
        int t = t0 + i;
        float d = g_dt[(b * Tdim + t) * NHdim + nh];
        prod *= expf(Anh * d);
    }
    float x = prod;
    #pragma unroll
    for (int off = 1; off < 32; off <<= 1) {
        float y = __shfl_up_sync(0xffffffffu, x, off);
        if (lane >= off) x *= y;
    }
    float excl = __shfl_up_sync(0xffffffffu, x, 1);
    if (lane == 0) excl = 1.f;
    float running = excl;
    float* prow = g_p + warp * Tdim;
    for (int i = 0; i < Tdim / 32; i++) {
        int t = t0 + i;
        float d = g_dt[(b * Tdim + t) * NHdim + nh];
        running *= expf(Anh * d);
        prow[t] = running;
    }
}

// ---------------- chunked scan of s = cumsum(beta*v/(p+EPS)) ----------------
__global__ void scan_partial_kernel() {
    int blk = blockIdx.x;
    int bnh = blk >> 6;
    int c = blk & (NCHUNK - 1);
    int b = bnh >> 4, nh = bnh & (NHdim - 1);
    int hd = threadIdx.x;
    const float* prow = g_p + bnh * Tdim;
    double s = 0.0;
    int t0 = c * CHUNK;
    for (int i = 0; i < CHUNK; i++) {
        int t = t0 + i;
        int m = b * Tdim + t;
        float beta = g_dt[m * NHdim + nh];
        float pv = prow[t];
        float v = g_v[(size_t)m * Hdim + nh * HDdim + hd];
        s += (double)((beta * v) / (pv + EPSf));
    }
    g_S[(size_t)blk * HDdim + hd] = s;
}

__global__ void scan_carry_kernel() {
    int bnh = blockIdx.x;
    int hd = threadIdx.x;
    double carry = 0.0;
    for (int c = 0; c < NCHUNK; c++) {
        size_t idx = ((size_t)bnh * NCHUNK + c) * HDdim + hd;
        g_carry[idx] = carry;
        carry += g_S[idx];
    }
}

__global__ void scan_final_kernel() {
    int blk = blockIdx.x;
    int bnh = blk >> 6;
    int c = blk & (NCHUNK - 1);
    int b = bnh >> 4, nh = bnh & (NHdim - 1);
    int hd = threadIdx.x;
    const float* prow = g_p + bnh * Tdim;
    double s = g_carry[(size_t)blk * HDdim + hd];
    int t0 = c * CHUNK;
    for (int i = 0; i < CHUNK; i++) {
        int t = t0 + i;
        int m = b * Tdim + t;
        float beta = g_dt[m * NHdim + nh];
        float pv = prow[t];
        size_t vidx = (size_t)m * Hdim + nh * HDdim + hd;
        float v = g_v[vidx];
        s += (double)((beta * v) / (pv + EPSf));
        float state = (float)((double)pv * s);
        g_scan[vidx] = g_q[vidx] * state;
    }
}

// ---------------- RoPE (in place on g_q) ----------------
__global__ void rope_kernel(const int* __restrict__ pos_ids) {
    size_t idx = (size_t)blockIdx.x * blockDim.x + threadIdx.x;
    size_t total = (size_t)Mdim * (Hdim / 2);
    if (idx >= total) return;
    int m = (int)(idx >> 10);
    int r = (int)(idx & 1023);
    int nh = r >> 6;
    int j = r & 63;
    int d0 = 2 * j;
    float pos = (float)pos_ids[m];
    size_t base = (size_t)m * Hdim + nh * HDdim + d0;
    float q0 = g_q[base], q1 = g_q[base + 1];
    float a0 = pos * g_invf[d0 & 63];
    float a1 = pos * g_invf[(d0 + 1) & 63];
    float c0 = cosf(a0), s0 = sinf(a0);
    float c1 = cosf(a1), s1 = sinf(a1);
    g_q[base]     = q0 * c0 - q1 * s0;
    g_q[base + 1] = q1 * c1 + q0 * s1;
}

// ---------------- launch ----------------
static void launch_gemm(const float* A, const float* B, float* C, int M, int N, int Kd,
                        const float* bias, const float* resid, bool conv, bool silu) {
    dim3 grid(N / BN, M / BM), block(256);
    if (conv)       mma_gemm_kernel<true,  true,  false, false><<<grid, block>>>(A, B, C, M, N, Kd, bias, nullptr);
    else if (silu)  mma_gemm_kernel<false, false, true,  false><<<grid, block>>>(A, B, C, M, N, Kd, nullptr, nullptr);
    else if (resid) mma_gemm_kernel<false, false, false, true ><<<grid, block>>>(A, B, C, M, N, Kd, nullptr, resid);
    else            mma_gemm_kernel<false, false, false, false><<<grid, block>>>(A, B, C, M, N, Kd, nullptr, nullptr);
}

extern "C" void kernel_launch(void* const* d_in, const int* in_sizes, int n_in,
                              void* d_out, int out_size) {
    const float* hidden  = (const float*)d_in[0];
    const int*   pos_ids = (const int*)  d_in[1];
    const float* conv_w  = (const float*)d_in[2];
    const float* conv_b  = (const float*)d_in[3];
    const float* wq      = (const float*)d_in[4];
    const float* wv      = (const float*)d_in[5];
    const float* w_dt    = (const float*)d_in[6];
    const float* b_dt    = (const float*)d_in[7];
    const float* A_log   = (const float*)d_in[8];
    const float* dt_bias = (const float*)d_in[9];
    const float* wo      = (const float*)d_in[10];
    const float* w1      = (const float*)d_in[11];
    const float* w2      = (const float*)d_in[12];
    const float* norm1_w = (const float*)d_in[13];
    const float* norm2_w = (const float*)d_in[14];
    float* out = (float*)d_out;

    float *p_wc, *p_norm, *p_x, *p_q, *p_v, *p_scan, *p_h2, *p_inter;
    cudaGetSymbolAddress((void**)&p_wc,    g_wc);
    cudaGetSymbolAddress((void**)&p_norm,  g_norm);
    cudaGetSymbolAddress((void**)&p_x,     g_x);
    cudaGetSymbolAddress((void**)&p_q,     g_q);
    cudaGetSymbolAddress((void**)&p_v,     g_v);
    cudaGetSymbolAddress((void**)&p_scan,  g_scan);
    cudaGetSymbolAddress((void**)&p_h2,    g_h2);
    cudaGetSymbolAddress((void**)&p_inter, g_inter);

    // init
    init_invf_kernel<<<1, 64>>>();
    {
        size_t total = (size_t)KCONV * Hdim * Hdim;
        pack_convw_kernel<<<(unsigned)((total + 255) / 256), 256>>>(conv_w);
    }

    // attn branch
    rmsnorm_kernel<<<Mdim, 256>>>(hidden, norm1_w, p_norm);
    launch_gemm(p_norm, p_wc, p_x, Mdim, Hdim, KCONV * Hdim, conv_b, nullptr, true, false); // conv
    launch_gemm(p_x, wq, p_q, Mdim, Hdim, Hdim, nullptr, nullptr, false, false);
    launch_gemm(p_x, wv, p_v, Mdim, Hdim, Hdim, nullptr, nullptr, false, false);
    {
        size_t pairs = (size_t)Mdim * (Hdim / 2);
        rope_kernel<<<(unsigned)((pairs + 255) / 256), 256>>>(pos_ids);
    }
    dt_kernel<<<Mdim, NHdim * 32>>>(w_dt, b_dt, dt_bias);
    p_scan_kernel<<<1, 1024>>>(A_log);
    scan_partial_kernel<<<Bdim * NHdim * NCHUNK, HDdim>>>();
    scan_carry_kernel<<<Bdim * NHdim, HDdim>>>();
    scan_final_kernel<<<Bdim * NHdim * NCHUNK, HDdim>>>();
    launch_gemm(p_scan, wo, p_h2, Mdim, Hdim, Hdim, nullptr, hidden, false, false);  // + residual

    // mlp branch
    rmsnorm_kernel<<<Mdim, 256>>>(p_h2, norm2_w, p_norm);
    launch_gemm(p_norm, w1, p_inter, Mdim, INTERd, Hdim, nullptr, nullptr, false, true);   // silu
    launch_gemm(p_inter, w2, out, Mdim, Hdim, INTERd, nullptr, p_h2, false, false);        // + residual
}